// round 15
// baseline (speedup 1.0000x reference)
#include <cuda_runtime.h>
#include <cuda_bf16.h>

#define NPIX (8*128*128)   // 131072 pixels
#define CCH  64

// Scratch (device globals). Activations NHWC.
__device__ __nv_bfloat16 g_hb0[(size_t)NPIX*CCH];
__device__ __nv_bfloat16 g_hb1[(size_t)NPIX*CCH];
__device__ __nv_bfloat16 g_qb[(size_t)NPIX*CCH];
__device__ __nv_bfloat16 g_kb[(size_t)NPIX*CCH];
__device__ __nv_bfloat16 g_vb[(size_t)NPIX*CCH];
__device__ __nv_bfloat16 g_wb[3*192*64];   // pre-converted [w1;w2;w3], k contiguous

__device__ __forceinline__ unsigned pack_bf(float a, float b) {
    __nv_bfloat162 h = __floats2bfloat162_rn(a, b);
    return *reinterpret_cast<unsigned*>(&h);
}
__device__ __forceinline__ void cp16(unsigned smem_dst, const void* gsrc) {
    asm volatile("cp.async.ca.shared.global [%0], [%1], 16;\n"
                 :: "r"(smem_dst), "l"(gsrc));
}
__device__ __forceinline__ float bflo(unsigned u) { return __uint_as_float(u << 16); }
__device__ __forceinline__ float bfhi(unsigned u) { return __uint_as_float(u & 0xffff0000u); }

// ---- packed f32x2 helpers (Blackwell FFMA2 path) ----
__device__ __forceinline__ unsigned long long bfpair(unsigned u) {
    // bf16x2 word -> f32x2 {lo_channel, hi_channel}
    unsigned lo = u << 16, hi = u & 0xffff0000u;
    unsigned long long r;
    asm("mov.b64 %0, {%1, %2};" : "=l"(r) : "r"(lo), "r"(hi));
    return r;
}
__device__ __forceinline__ unsigned long long pk2(float a, float b) {
    unsigned long long r;
    asm("mov.b64 %0, {%1, %2};" : "=l"(r) : "f"(a), "f"(b));
    return r;
}
__device__ __forceinline__ void fma2(unsigned long long& acc,
                                     unsigned long long a, unsigned long long b) {
    asm("fma.rn.f32x2 %0, %1, %2, %0;" : "+l"(acc) : "l"(a), "l"(b));
}
__device__ __forceinline__ void unpk2(float& a, float& b, unsigned long long v) {
    asm("mov.b64 {%0, %1}, %2;" : "=f"(a), "=f"(b) : "l"(v));
}

#define MMA(c, a0,a1,a2,a3, b0,b1) \
    asm volatile("mma.sync.aligned.m16n8k16.row.col.f32.bf16.bf16.f32 " \
                 "{%0,%1,%2,%3}, {%4,%5,%6,%7}, {%8,%9}, {%0,%1,%2,%3};" \
                 : "+f"(c[0]), "+f"(c[1]), "+f"(c[2]), "+f"(c[3]) \
                 : "r"(a0), "r"(a1), "r"(a2), "r"(a3), "r"(b0), "r"(b1))

// ---------------------------------------------------------------------------
// weight convert: 9 x [64x64] fp32 -> bf16 [3][192][64], single launch
// ---------------------------------------------------------------------------
__global__ void convert_w_k(const float* w0, const float* w1, const float* w2,
                            const float* w3, const float* w4, const float* w5,
                            const float* w6, const float* w7, const float* w8,
                            __nv_bfloat16* __restrict__ dst) {
    int idx = blockIdx.x*256 + threadIdx.x;       // 0..36863
    if (idx >= 3*192*64) return;
    const float* tbl[9] = {w0,w1,w2,w3,w4,w5,w6,w7,w8};
    int layer = idx / 12288, r = idx % 12288;
    const float* src = tbl[layer*3 + r/4096];
    dst[idx] = __float2bfloat16(src[r & 4095]);
}

// ---------------------------------------------------------------------------
// conv_in: x NCHW -> relu(conv3x3) -> NHWC bf16.
// Round-8 proven version: 16x16 tile, halo 18x18x3 smem, 1 thread/pixel.
// ---------------------------------------------------------------------------
__global__ __launch_bounds__(256) void conv_in_k(const float* __restrict__ x,
                                                 const float* __restrict__ w,
                                                 __nv_bfloat16* __restrict__ out) {
    __shared__ float ws[64*27];            // [o][c*9+dy*3+dx] (OIHW order)
    __shared__ float xs[3][18][18];
    int tid = threadIdx.x;
    int bx = blockIdx.x, by = blockIdx.y, n = blockIdx.z;
    int y0 = by*16, x0 = bx*16;

    for (int i = tid; i < 64*27; i += 256) ws[i] = w[i];
    for (int idx = tid; idx < 972; idx += 256) {
        int c = idx / 324, r = idx % 324;
        int yy = y0 + r/18 - 1, xx = x0 + r%18 - 1;
        float v = 0.f;
        if (yy >= 0 && yy < 128 && xx >= 0 && xx < 128)
            v = x[((n*3 + c) << 14) + (yy << 7) + xx];
        xs[c][r/18][r%18] = v;
    }
    __syncthreads();

    int py = tid >> 4, px = tid & 15;
    float v[27];
    int t = 0;
    #pragma unroll
    for (int c = 0; c < 3; c++)
        #pragma unroll
        for (int dy = 0; dy < 3; dy++)
            #pragma unroll
            for (int dx = 0; dx < 3; dx++, t++)
                v[t] = xs[c][py+dy][px+dx];

    size_t obase = (((size_t)n << 14) + ((size_t)(y0+py) << 7) + (x0+px)) * 64;
    #pragma unroll
    for (int ch = 0; ch < 4; ch++) {
        float r[16];
        #pragma unroll
        for (int j = 0; j < 16; j++) {
            int o = ch*16 + j;
            float acc = 0.f;
            #pragma unroll
            for (int tt = 0; tt < 27; tt++) acc = fmaf(v[tt], ws[o*27 + tt], acc);
            r[j] = fmaxf(acc, 0.f);
        }
        uint4 u0 = make_uint4(pack_bf(r[0],r[1]),  pack_bf(r[2],r[3]),
                              pack_bf(r[4],r[5]),  pack_bf(r[6],r[7]));
        uint4 u1 = make_uint4(pack_bf(r[8],r[9]),  pack_bf(r[10],r[11]),
                              pack_bf(r[12],r[13]),pack_bf(r[14],r[15]));
        ((uint4*)(out + obase + ch*16))[0] = u0;
        ((uint4*)(out + obase + ch*16))[1] = u1;
    }
}

// ---------------------------------------------------------------------------
// qkv: fused triple 1x1 via bf16 mma. Block = 64 px x 192 outs (proven core).
// Epilogue: q, k, v all packed bf16.
// ---------------------------------------------------------------------------
__global__ __launch_bounds__(256) void qkv_k(const __nv_bfloat16* __restrict__ in,
                                             const __nv_bfloat16* __restrict__ wb,
                                             __nv_bfloat16* __restrict__ qo,
                                             __nv_bfloat16* __restrict__ ko,
                                             __nv_bfloat16* __restrict__ vo) {
    __shared__ __nv_bfloat16 a_s[64*72];
    __shared__ __nv_bfloat16 w_s[192*72];
    int tid = threadIdx.x;
    size_t pix0 = (size_t)blockIdx.x * 64;

    unsigned a_base = (unsigned)__cvta_generic_to_shared(a_s);
    unsigned w_base = (unsigned)__cvta_generic_to_shared(w_s);

    #pragma unroll
    for (int i = 0; i < 2; i++) {
        int idx = tid + 256*i;
        int row = idx >> 3, c8 = idx & 7;
        cp16(a_base + row*144 + c8*16, in + pix0*64 + (size_t)idx*8);
    }
    #pragma unroll
    for (int i = 0; i < 6; i++) {
        int idx = tid + 256*i;
        int row = idx >> 3, c8 = idx & 7;
        cp16(w_base + row*144 + c8*16, wb + row*64 + c8*8);
    }
    asm volatile("cp.async.commit_group;\n" ::: "memory");
    asm volatile("cp.async.wait_group 0;\n" ::: "memory");
    __syncthreads();

    int lane = tid & 31, w = tid >> 5;
    int wm = (w >> 1) * 16;
    int wn = (w & 1) * 96;
    int lr = lane >> 2, lc = lane & 3;

    float c[12][4];
    #pragma unroll
    for (int t = 0; t < 12; t++)
        #pragma unroll
        for (int i = 0; i < 4; i++) c[t][i] = 0.f;

    #pragma unroll
    for (int ks = 0; ks < 4; ks++) {
        int k0 = ks*16;
        unsigned a0 = *(const unsigned*)&a_s[(wm+lr  )*72 + k0 + lc*2    ];
        unsigned a1 = *(const unsigned*)&a_s[(wm+lr+8)*72 + k0 + lc*2    ];
        unsigned a2 = *(const unsigned*)&a_s[(wm+lr  )*72 + k0 + lc*2 + 8];
        unsigned a3 = *(const unsigned*)&a_s[(wm+lr+8)*72 + k0 + lc*2 + 8];
        #pragma unroll
        for (int t = 0; t < 12; t++) {
            int bc = wn + t*8 + lr;
            unsigned b0 = *(const unsigned*)&w_s[bc*72 + k0 + lc*2    ];
            unsigned b1 = *(const unsigned*)&w_s[bc*72 + k0 + lc*2 + 8];
            MMA(c[t], a0,a1,a2,a3, b0,b1);
        }
    }

    size_t pixA = pix0 + wm + lr;
    size_t pixB = pixA + 8;
    #pragma unroll
    for (int t = 0; t < 12; t++) {
        int n0 = wn + t*8 + lc*2;
        __nv_bfloat16* dst = (n0 < 64) ? qo : (n0 < 128) ? ko : vo;
        int ch = n0 & 63;
        *(unsigned*)(dst + pixA*64 + ch) = pack_bf(c[t][0], c[t][1]);
        *(unsigned*)(dst + pixB*64 + ch) = pack_bf(c[t][2], c[t][3]);
    }
}

// ---------------------------------------------------------------------------
// attn: 5x5 local attention + relu. bf16 q/k/v; tile 8x4, 8 thr/px.
// FFMA2 (f32x2) packed math in both hot loops; no max-subtraction; exp fused
// into similarity loop (tap owner computes it right after shfl-reduce).
// ---------------------------------------------------------------------------
#define KROW8 72

__global__ __launch_bounds__(256, 4) void attn_k(const __nv_bfloat16* __restrict__ xq,
                                                 const __nv_bfloat16* __restrict__ xk,
                                                 const __nv_bfloat16* __restrict__ xv,
                                                 __nv_bfloat16* __restrict__ outb) {
    __shared__ __nv_bfloat16 k_s[96*KROW8];
    __shared__ __nv_bfloat16 v_s[96*KROW8];
    __shared__ float wgt_s[32*26];
    int tid = threadIdx.x;
    int bx = blockIdx.x, by = blockIdx.y, n = blockIdx.z;
    int y0 = by*4, x0 = bx*8;

    for (int idx = tid; idx < 96*8; idx += 256) {
        int hp = idx >> 3, c8 = idx & 7;
        int yy = y0 + (hp/12) - 2, xx = x0 + (hp%12) - 2;
        uint4 kv = make_uint4(0,0,0,0), vv = make_uint4(0,0,0,0);
        if (yy >= 0 && yy < 128 && xx >= 0 && xx < 128) {
            size_t base = (((size_t)n << 14) + (yy << 7) + xx) * 8;
            kv = ((const uint4*)xk)[base + c8];
            vv = ((const uint4*)xv)[base + c8];
        }
        ((uint4*)(k_s + hp*KROW8))[c8] = kv;
        ((uint4*)(v_s + hp*KROW8))[c8] = vv;
    }
    __syncthreads();

    int pix = tid >> 3, q = tid & 7;
    int py = pix >> 3, px = pix & 7;

    // q: one uint4 = 8 bf16 channels, kept as 4 packed f32x2
    unsigned long long qp2[4];
    {
        size_t gb = (((size_t)n << 14) + ((size_t)(y0+py) << 7) + (x0+px))*64 + q*8;
        uint4 uq = *(const uint4*)(xq + gb);
        qp2[0] = bfpair(uq.x); qp2[1] = bfpair(uq.y);
        qp2[2] = bfpair(uq.z); qp2[3] = bfpair(uq.w);
    }

    // similarity (+ fused exp, no max-subtraction — ratios identical)
    float psum = 0.f;
    #pragma unroll
    for (int dy = 0; dy < 5; dy++)
        #pragma unroll
        for (int dx = 0; dx < 5; dx++) {
            int nb = (py+dy)*12 + (px+dx);
            uint4 ka = *(const uint4*)(k_s + nb*KROW8 + q*8);
            unsigned long long s2 = 0ull;
            fma2(s2, bfpair(ka.x), qp2[0]);
            fma2(s2, bfpair(ka.y), qp2[1]);
            fma2(s2, bfpair(ka.z), qp2[2]);
            fma2(s2, bfpair(ka.w), qp2[3]);
            float slo, shi; unpk2(slo, shi, s2);
            float s = slo + shi;
            s += __shfl_xor_sync(0xffffffffu, s, 1);
            s += __shfl_xor_sync(0xffffffffu, s, 2);
            s += __shfl_xor_sync(0xffffffffu, s, 4);
            int t = dy*5 + dx;
            if ((t & 7) == q) {
                float e = __expf(s);
                wgt_s[pix*26 + t] = e;
                psum += e;
            }
        }
    psum += __shfl_xor_sync(0xffffffffu, psum, 1);
    psum += __shfl_xor_sync(0xffffffffu, psum, 2);
    psum += __shfl_xor_sync(0xffffffffu, psum, 4);
    float inv = 1.f / psum;
    __syncwarp();

    // aggregation with packed FFMA2
    unsigned long long o2[4] = {0ull, 0ull, 0ull, 0ull};
    #pragma unroll
    for (int dy = 0; dy < 5; dy++)
        #pragma unroll
        for (int dx = 0; dx < 5; dx++) {
            int nb = (py+dy)*12 + (px+dx);
            float wk = wgt_s[pix*26 + dy*5 + dx];
            unsigned long long wk2 = pk2(wk, wk);
            uint4 va = *(const uint4*)(v_s + nb*KROW8 + q*8);
            fma2(o2[0], bfpair(va.x), wk2);
            fma2(o2[1], bfpair(va.y), wk2);
            fma2(o2[2], bfpair(va.z), wk2);
            fma2(o2[3], bfpair(va.w), wk2);
        }

    float o[8];
    unpk2(o[0], o[1], o2[0]); unpk2(o[2], o[3], o2[1]);
    unpk2(o[4], o[5], o2[2]); unpk2(o[6], o[7], o2[3]);

    size_t base = (((size_t)n << 14) + ((size_t)(y0+py) << 7) + (x0+px))*64 + q*8;
    uint4 u = make_uint4(pack_bf(fmaxf(o[0]*inv,0.f), fmaxf(o[1]*inv,0.f)),
                         pack_bf(fmaxf(o[2]*inv,0.f), fmaxf(o[3]*inv,0.f)),
                         pack_bf(fmaxf(o[4]*inv,0.f), fmaxf(o[5]*inv,0.f)),
                         pack_bf(fmaxf(o[6]*inv,0.f), fmaxf(o[7]*inv,0.f)));
    *(uint4*)(outb + base) = u;
}

// ---------------------------------------------------------------------------
// conv_out + residual: h NHWC bf16 -> conv3x3 (64->3) + x -> NCHW fp32.
// ---------------------------------------------------------------------------
#define COP 72

__global__ __launch_bounds__(256) void conv_out_k(const __nv_bfloat16* __restrict__ h,
                                                  const float* __restrict__ w,
                                                  const float* __restrict__ xin,
                                                  float* __restrict__ out) {
    extern __shared__ char smc[];
    float* ws = (float*)smc;                          // 1728 floats [tap][o][c]
    __nv_bfloat16* hs = (__nv_bfloat16*)(smc + 6912); // 324 x COP
    int tid = threadIdx.x;
    int bx = blockIdx.x, by = blockIdx.y, n = blockIdx.z;
    int y0 = by*16, x0 = bx*16;

    for (int idx = tid; idx < 1728; idx += 256) {
        int tap = idx / 192, r = idx % 192, o = r >> 6, c = r & 63;
        ws[idx] = w[(o*64 + c)*9 + tap];
    }
    for (int idx = tid; idx < 324*8; idx += 256) {
        int hp = idx >> 3, c8 = idx & 7;
        int yy = y0 + hp/18 - 1, xx = x0 + hp%18 - 1;
        uint4 val = make_uint4(0,0,0,0);
        if (yy >= 0 && yy < 128 && xx >= 0 && xx < 128)
            val = ((const uint4*)(h + (((size_t)n << 14) + (yy << 7) + xx)*64))[c8];
        ((uint4*)(hs + hp*COP))[c8] = val;
    }
    __syncthreads();

    int py = tid >> 4, px = tid & 15;
    float acc0 = 0.f, acc1 = 0.f, acc2 = 0.f;
    #pragma unroll
    for (int dy = 0; dy < 3; dy++)
        #pragma unroll
        for (int dx = 0; dx < 3; dx++) {
            int tap = dy*3 + dx;
            const __nv_bfloat16* hp = hs + ((py+dy)*18 + (px+dx))*COP;
            const float* wp = ws + tap*192;
            #pragma unroll
            for (int c8 = 0; c8 < 8; c8++) {
                uint4 hv = ((const uint4*)hp)[c8];
                float f[8] = { bflo(hv.x), bfhi(hv.x), bflo(hv.y), bfhi(hv.y),
                               bflo(hv.z), bfhi(hv.z), bflo(hv.w), bfhi(hv.w) };
                #pragma unroll
                for (int j = 0; j < 8; j++) {
                    int c = c8*8 + j;
                    acc0 = fmaf(f[j], wp[c      ], acc0);
                    acc1 = fmaf(f[j], wp[c +  64], acc1);
                    acc2 = fmaf(f[j], wp[c + 128], acc2);
                }
            }
        }

    int po = ((y0+py) << 7) + (x0+px);
    out[((n*3 + 0) << 14) + po] = acc0 + xin[((n*3 + 0) << 14) + po];
    out[((n*3 + 1) << 14) + po] = acc1 + xin[((n*3 + 1) << 14) + po];
    out[((n*3 + 2) << 14) + po] = acc2 + xin[((n*3 + 2) << 14) + po];
}

// ---------------------------------------------------------------------------
extern "C" void kernel_launch(void* const* d_in, const int* in_sizes, int n_in,
                              void* d_out, int out_size) {
    const float* x       = (const float*)d_in[0];
    const float* conv_in = (const float*)d_in[1];
    const float* W[9];
    for (int i = 0; i < 9; i++) W[i] = (const float*)d_in[2 + i];
    const float* conv_out = (const float*)d_in[11];
    float* out = (float*)d_out;

    __nv_bfloat16 *H0, *H1, *Q, *K, *V, *WB;
    cudaGetSymbolAddress((void**)&H0, g_hb0);
    cudaGetSymbolAddress((void**)&H1, g_hb1);
    cudaGetSymbolAddress((void**)&Q,  g_qb);
    cudaGetSymbolAddress((void**)&K,  g_kb);
    cudaGetSymbolAddress((void**)&V,  g_vb);
    cudaGetSymbolAddress((void**)&WB, g_wb);

    size_t co_smem = 6912 + (size_t)324*COP*sizeof(__nv_bfloat16);   // ~53.6 KB
    cudaFuncSetAttribute(conv_out_k, cudaFuncAttributeMaxDynamicSharedMemorySize, (int)co_smem);

    convert_w_k<<<144, 256>>>(W[0], W[1], W[2], W[3], W[4], W[5], W[6], W[7], W[8], WB);

    conv_in_k<<<dim3(8,8,8), 256>>>(x, conv_in, H0);

    dim3 agrid(16, 32, 8);
    // layer 0: H0 -> H1
    qkv_k<<<NPIX/64, 256>>>(H0, WB, Q, K, V);
    attn_k<<<agrid, 256>>>(Q, K, V, H1);
    // layer 1: H1 -> H0
    qkv_k<<<NPIX/64, 256>>>(H1, WB + 192*64, Q, K, V);
    attn_k<<<agrid, 256>>>(Q, K, V, H0);
    // layer 2: H0 -> H1
    qkv_k<<<NPIX/64, 256>>>(H0, WB + 2*192*64, Q, K, V);
    attn_k<<<agrid, 256>>>(Q, K, V, H1);

    conv_out_k<<<dim3(8,8,8), 256, co_smem>>>(H1, conv_out, x, out);
}

// round 16
// speedup vs baseline: 1.0402x; 1.0402x over previous
#include <cuda_runtime.h>
#include <cuda_bf16.h>

#define NPIX (8*128*128)   // 131072 pixels
#define CCH  64

// Scratch (device globals). Activations NHWC.
__device__ __nv_bfloat16 g_hb0[(size_t)NPIX*CCH];
__device__ __nv_bfloat16 g_hb1[(size_t)NPIX*CCH];
__device__ __nv_bfloat16 g_qb[(size_t)NPIX*CCH];
__device__ __nv_bfloat16 g_kb[(size_t)NPIX*CCH];
__device__ __nv_bfloat16 g_vb[(size_t)NPIX*CCH];
__device__ __nv_bfloat16 g_wb[3*192*64];   // attn weights [w1;w2;w3], k contiguous
__device__ __nv_bfloat16 g_wci[64*64];     // conv_in weights [o][k], k: taps hi 0-26, lo 32-58

__device__ __forceinline__ unsigned pack_bf(float a, float b) {
    __nv_bfloat162 h = __floats2bfloat162_rn(a, b);
    return *reinterpret_cast<unsigned*>(&h);
}
__device__ __forceinline__ unsigned pack2h(__nv_bfloat16 a, __nv_bfloat16 b) {
    __nv_bfloat162 h = __halves2bfloat162(a, b);
    return *reinterpret_cast<unsigned*>(&h);
}
__device__ __forceinline__ void cp16(unsigned smem_dst, const void* gsrc) {
    asm volatile("cp.async.ca.shared.global [%0], [%1], 16;\n"
                 :: "r"(smem_dst), "l"(gsrc));
}
__device__ __forceinline__ float bflo(unsigned u) { return __uint_as_float(u << 16); }
__device__ __forceinline__ float bfhi(unsigned u) { return __uint_as_float(u & 0xffff0000u); }

#define MMA(c, a0,a1,a2,a3, b0,b1) \
    asm volatile("mma.sync.aligned.m16n8k16.row.col.f32.bf16.bf16.f32 " \
                 "{%0,%1,%2,%3}, {%4,%5,%6,%7}, {%8,%9}, {%0,%1,%2,%3};" \
                 : "+f"(c[0]), "+f"(c[1]), "+f"(c[2]), "+f"(c[3]) \
                 : "r"(a0), "r"(a1), "r"(a2), "r"(a3), "r"(b0), "r"(b1))

// ---------------------------------------------------------------------------
// weight converts (once per run)
// ---------------------------------------------------------------------------
__global__ void convert_w_k(const float* w0, const float* w1, const float* w2,
                            const float* w3, const float* w4, const float* w5,
                            const float* w6, const float* w7, const float* w8,
                            __nv_bfloat16* __restrict__ dst) {
    int idx = blockIdx.x*256 + threadIdx.x;       // 0..36863
    if (idx >= 3*192*64) return;
    const float* tbl[9] = {w0,w1,w2,w3,w4,w5,w6,w7,w8};
    int layer = idx / 12288, r = idx % 12288;
    const float* src = tbl[layer*3 + r/4096];
    dst[idx] = __float2bfloat16(src[r & 4095]);
}

// conv_in weights: [64][27] fp32 -> [64][64] bf16, tap t duplicated at k=t and k=32+t
__global__ void convert_wc_k(const float* __restrict__ w, __nv_bfloat16* __restrict__ dst) {
    int idx = blockIdx.x*256 + threadIdx.x;       // 0..4095
    if (idx >= 64*64) return;
    int o = idx >> 6, k = idx & 63;
    int t = k & 31;
    __nv_bfloat16 v = __float2bfloat16(0.f);
    if (t < 27) v = __float2bfloat16(w[o*27 + t]);
    dst[idx] = v;
}

// ---------------------------------------------------------------------------
// conv_in via tensor cores: im2col A [64px x 64k] (hi/lo split x) @ W^T.
// Block = 8x8 pixel tile; halo 10x10x3 fp32 smem; mma identical to qkv core.
// ---------------------------------------------------------------------------
__global__ __launch_bounds__(256) void conv_in_k(const float* __restrict__ x,
                                                 const __nv_bfloat16* __restrict__ wci,
                                                 __nv_bfloat16* __restrict__ out) {
    __shared__ float xs[3][10][10];
    __shared__ __nv_bfloat16 a_s[64*72];
    __shared__ __nv_bfloat16 w_s[64*72];
    int tid = threadIdx.x;
    int bx = blockIdx.x, by = blockIdx.y, n = blockIdx.z;
    int y0 = by*8, x0 = bx*8;

    // W: 64 rows x 64 bf16 via cp.async
    unsigned w_base = (unsigned)__cvta_generic_to_shared(w_s);
    #pragma unroll
    for (int i = 0; i < 2; i++) {
        int idx = tid + 256*i;
        int row = idx >> 3, c8 = idx & 7;
        cp16(w_base + row*144 + c8*16, wci + row*64 + c8*8);
    }
    asm volatile("cp.async.commit_group;\n" ::: "memory");

    // halo 10x10x3 fp32
    for (int idx = tid; idx < 300; idx += 256) {
        int c = idx / 100, r = idx % 100;
        int yy = y0 + r/10 - 1, xx = x0 + r%10 - 1;
        float v = 0.f;
        if (yy >= 0 && yy < 128 && xx >= 0 && xx < 128)
            v = x[((n*3 + c) << 14) + (yy << 7) + xx];
        xs[c][r/10][r%10] = v;
    }
    asm volatile("cp.async.wait_group 0;\n" ::: "memory");
    __syncthreads();

    // build A: thread = (pixel, kgroup of 16)
    {
        int pxl = tid >> 2, kg = tid & 3;
        int ppy = pxl >> 3, ppx = pxl & 7;
        unsigned pk[8];
        #pragma unroll
        for (int j2 = 0; j2 < 8; j2++) {
            __nv_bfloat16 h0, h1;
            #pragma unroll
            for (int s = 0; s < 2; s++) {
                int k = kg*16 + j2*2 + s;
                int t = k & 31;
                bool lo = (k >= 32);
                __nv_bfloat16 hv = __float2bfloat16(0.f);
                if (t < 27) {
                    int c = t / 9, r = t % 9;
                    float xv = xs[c][ppy + r/3][ppx + r%3];
                    __nv_bfloat16 hb = __float2bfloat16(xv);
                    hv = lo ? __float2bfloat16(xv - __bfloat162float(hb)) : hb;
                }
                if (s == 0) h0 = hv; else h1 = hv;
            }
            pk[j2] = pack2h(h0, h1);
        }
        uint4* dst4 = (uint4*)(a_s + pxl*72 + kg*16);
        dst4[0] = make_uint4(pk[0], pk[1], pk[2], pk[3]);
        dst4[1] = make_uint4(pk[4], pk[5], pk[6], pk[7]);
    }
    __syncthreads();

    int lane = tid & 31, w = tid >> 5;
    int wm = (w >> 1) * 16;        // 4 m-groups of 16 px
    int wn = (w & 1) * 32;         // 2 n-groups of 32 outs
    int lr = lane >> 2, lc = lane & 3;

    float c[4][4];
    #pragma unroll
    for (int t = 0; t < 4; t++)
        #pragma unroll
        for (int i = 0; i < 4; i++) c[t][i] = 0.f;

    #pragma unroll
    for (int ks = 0; ks < 4; ks++) {
        int k0 = ks*16;
        unsigned a0 = *(const unsigned*)&a_s[(wm+lr  )*72 + k0 + lc*2    ];
        unsigned a1 = *(const unsigned*)&a_s[(wm+lr+8)*72 + k0 + lc*2    ];
        unsigned a2 = *(const unsigned*)&a_s[(wm+lr  )*72 + k0 + lc*2 + 8];
        unsigned a3 = *(const unsigned*)&a_s[(wm+lr+8)*72 + k0 + lc*2 + 8];
        #pragma unroll
        for (int t = 0; t < 4; t++) {
            int bc = wn + t*8 + lr;
            unsigned b0 = *(const unsigned*)&w_s[bc*72 + k0 + lc*2    ];
            unsigned b1 = *(const unsigned*)&w_s[bc*72 + k0 + lc*2 + 8];
            MMA(c[t], a0,a1,a2,a3, b0,b1);
        }
    }

    // epilogue: relu -> bf16 NHWC
    int p0 = wm + lr, p1 = p0 + 8;
    size_t g0 = (((size_t)n << 14) + ((size_t)(y0 + (p0>>3)) << 7) + (x0 + (p0&7)))*64;
    size_t g1 = (((size_t)n << 14) + ((size_t)(y0 + (p1>>3)) << 7) + (x0 + (p1&7)))*64;
    #pragma unroll
    for (int t = 0; t < 4; t++) {
        int n0 = wn + t*8 + lc*2;
        *(unsigned*)(out + g0 + n0) = pack_bf(fmaxf(c[t][0],0.f), fmaxf(c[t][1],0.f));
        *(unsigned*)(out + g1 + n0) = pack_bf(fmaxf(c[t][2],0.f), fmaxf(c[t][3],0.f));
    }
}

// ---------------------------------------------------------------------------
// qkv: fused triple 1x1 via bf16 mma. Block = 64 px x 192 outs (proven core).
// ---------------------------------------------------------------------------
__global__ __launch_bounds__(256) void qkv_k(const __nv_bfloat16* __restrict__ in,
                                             const __nv_bfloat16* __restrict__ wb,
                                             __nv_bfloat16* __restrict__ qo,
                                             __nv_bfloat16* __restrict__ ko,
                                             __nv_bfloat16* __restrict__ vo) {
    __shared__ __nv_bfloat16 a_s[64*72];
    __shared__ __nv_bfloat16 w_s[192*72];
    int tid = threadIdx.x;
    size_t pix0 = (size_t)blockIdx.x * 64;

    unsigned a_base = (unsigned)__cvta_generic_to_shared(a_s);
    unsigned w_base = (unsigned)__cvta_generic_to_shared(w_s);

    #pragma unroll
    for (int i = 0; i < 2; i++) {
        int idx = tid + 256*i;
        int row = idx >> 3, c8 = idx & 7;
        cp16(a_base + row*144 + c8*16, in + pix0*64 + (size_t)idx*8);
    }
    #pragma unroll
    for (int i = 0; i < 6; i++) {
        int idx = tid + 256*i;
        int row = idx >> 3, c8 = idx & 7;
        cp16(w_base + row*144 + c8*16, wb + row*64 + c8*8);
    }
    asm volatile("cp.async.commit_group;\n" ::: "memory");
    asm volatile("cp.async.wait_group 0;\n" ::: "memory");
    __syncthreads();

    int lane = tid & 31, w = tid >> 5;
    int wm = (w >> 1) * 16;
    int wn = (w & 1) * 96;
    int lr = lane >> 2, lc = lane & 3;

    float c[12][4];
    #pragma unroll
    for (int t = 0; t < 12; t++)
        #pragma unroll
        for (int i = 0; i < 4; i++) c[t][i] = 0.f;

    #pragma unroll
    for (int ks = 0; ks < 4; ks++) {
        int k0 = ks*16;
        unsigned a0 = *(const unsigned*)&a_s[(wm+lr  )*72 + k0 + lc*2    ];
        unsigned a1 = *(const unsigned*)&a_s[(wm+lr+8)*72 + k0 + lc*2    ];
        unsigned a2 = *(const unsigned*)&a_s[(wm+lr  )*72 + k0 + lc*2 + 8];
        unsigned a3 = *(const unsigned*)&a_s[(wm+lr+8)*72 + k0 + lc*2 + 8];
        #pragma unroll
        for (int t = 0; t < 12; t++) {
            int bc = wn + t*8 + lr;
            unsigned b0 = *(const unsigned*)&w_s[bc*72 + k0 + lc*2    ];
            unsigned b1 = *(const unsigned*)&w_s[bc*72 + k0 + lc*2 + 8];
            MMA(c[t], a0,a1,a2,a3, b0,b1);
        }
    }

    size_t pixA = pix0 + wm + lr;
    size_t pixB = pixA + 8;
    #pragma unroll
    for (int t = 0; t < 12; t++) {
        int n0 = wn + t*8 + lc*2;
        __nv_bfloat16* dst = (n0 < 64) ? qo : (n0 < 128) ? ko : vo;
        int ch = n0 & 63;
        *(unsigned*)(dst + pixA*64 + ch) = pack_bf(c[t][0], c[t][1]);
        *(unsigned*)(dst + pixB*64 + ch) = pack_bf(c[t][2], c[t][3]);
    }
}

// ---------------------------------------------------------------------------
// attn: 5x5 local attention + relu (round-14 proven version, verbatim).
// ---------------------------------------------------------------------------
#define KROW8 72

__global__ __launch_bounds__(256, 4) void attn_k(const __nv_bfloat16* __restrict__ xq,
                                                 const __nv_bfloat16* __restrict__ xk,
                                                 const __nv_bfloat16* __restrict__ xv,
                                                 __nv_bfloat16* __restrict__ outb) {
    __shared__ __nv_bfloat16 k_s[96*KROW8];
    __shared__ __nv_bfloat16 v_s[96*KROW8];
    __shared__ float wgt_s[32*26];
    int tid = threadIdx.x;
    int bx = blockIdx.x, by = blockIdx.y, n = blockIdx.z;
    int y0 = by*4, x0 = bx*8;

    for (int idx = tid; idx < 96*8; idx += 256) {
        int hp = idx >> 3, c8 = idx & 7;
        int yy = y0 + (hp/12) - 2, xx = x0 + (hp%12) - 2;
        uint4 kv = make_uint4(0,0,0,0), vv = make_uint4(0,0,0,0);
        if (yy >= 0 && yy < 128 && xx >= 0 && xx < 128) {
            size_t base = (((size_t)n << 14) + (yy << 7) + xx) * 8;
            kv = ((const uint4*)xk)[base + c8];
            vv = ((const uint4*)xv)[base + c8];
        }
        ((uint4*)(k_s + hp*KROW8))[c8] = kv;
        ((uint4*)(v_s + hp*KROW8))[c8] = vv;
    }
    __syncthreads();

    int pix = tid >> 3, q = tid & 7;
    int py = pix >> 3, px = pix & 7;

    float qr[8];
    {
        size_t gb = (((size_t)n << 14) + ((size_t)(y0+py) << 7) + (x0+px))*64 + q*8;
        uint4 uq = *(const uint4*)(xq + gb);
        qr[0]=bflo(uq.x); qr[1]=bfhi(uq.x); qr[2]=bflo(uq.y); qr[3]=bfhi(uq.y);
        qr[4]=bflo(uq.z); qr[5]=bfhi(uq.z); qr[6]=bflo(uq.w); qr[7]=bfhi(uq.w);
    }

    float m = -1e30f;
    #pragma unroll
    for (int dy = 0; dy < 5; dy++)
        #pragma unroll
        for (int dx = 0; dx < 5; dx++) {
            int nb = (py+dy)*12 + (px+dx);
            uint4 ka = *(const uint4*)(k_s + nb*KROW8 + q*8);
            float s = 0.f;
            s = fmaf(bflo(ka.x), qr[0], s); s = fmaf(bfhi(ka.x), qr[1], s);
            s = fmaf(bflo(ka.y), qr[2], s); s = fmaf(bfhi(ka.y), qr[3], s);
            s = fmaf(bflo(ka.z), qr[4], s); s = fmaf(bfhi(ka.z), qr[5], s);
            s = fmaf(bflo(ka.w), qr[6], s); s = fmaf(bfhi(ka.w), qr[7], s);
            s += __shfl_xor_sync(0xffffffffu, s, 1);
            s += __shfl_xor_sync(0xffffffffu, s, 2);
            s += __shfl_xor_sync(0xffffffffu, s, 4);
            wgt_s[pix*26 + dy*5 + dx] = s;
            m = fmaxf(m, s);
        }
    __syncwarp();

    float psum = 0.f;
    for (int t = q; t < 25; t += 8) {
        float e = __expf(wgt_s[pix*26 + t] - m);
        wgt_s[pix*26 + t] = e;
        psum += e;
    }
    psum += __shfl_xor_sync(0xffffffffu, psum, 1);
    psum += __shfl_xor_sync(0xffffffffu, psum, 2);
    psum += __shfl_xor_sync(0xffffffffu, psum, 4);
    float inv = 1.f / psum;
    __syncwarp();

    float o[8];
    #pragma unroll
    for (int i = 0; i < 8; i++) o[i] = 0.f;
    #pragma unroll
    for (int dy = 0; dy < 5; dy++)
        #pragma unroll
        for (int dx = 0; dx < 5; dx++) {
            int nb = (py+dy)*12 + (px+dx);
            float wk = wgt_s[pix*26 + dy*5 + dx];
            uint4 va = *(const uint4*)(v_s + nb*KROW8 + q*8);
            o[0] = fmaf(wk, bflo(va.x), o[0]); o[1] = fmaf(wk, bfhi(va.x), o[1]);
            o[2] = fmaf(wk, bflo(va.y), o[2]); o[3] = fmaf(wk, bfhi(va.y), o[3]);
            o[4] = fmaf(wk, bflo(va.z), o[4]); o[5] = fmaf(wk, bfhi(va.z), o[5]);
            o[6] = fmaf(wk, bflo(va.w), o[6]); o[7] = fmaf(wk, bfhi(va.w), o[7]);
        }

    size_t base = (((size_t)n << 14) + ((size_t)(y0+py) << 7) + (x0+px))*64 + q*8;
    uint4 u = make_uint4(pack_bf(fmaxf(o[0]*inv,0.f), fmaxf(o[1]*inv,0.f)),
                         pack_bf(fmaxf(o[2]*inv,0.f), fmaxf(o[3]*inv,0.f)),
                         pack_bf(fmaxf(o[4]*inv,0.f), fmaxf(o[5]*inv,0.f)),
                         pack_bf(fmaxf(o[6]*inv,0.f), fmaxf(o[7]*inv,0.f)));
    *(uint4*)(outb + base) = u;
}

// ---------------------------------------------------------------------------
// conv_out + residual: h NHWC bf16 -> conv3x3 (64->3) + x -> NCHW fp32.
// ---------------------------------------------------------------------------
#define COP 72

__global__ __launch_bounds__(256) void conv_out_k(const __nv_bfloat16* __restrict__ h,
                                                  const float* __restrict__ w,
                                                  const float* __restrict__ xin,
                                                  float* __restrict__ out) {
    extern __shared__ char smc[];
    float* ws = (float*)smc;                          // 1728 floats [tap][o][c]
    __nv_bfloat16* hs = (__nv_bfloat16*)(smc + 6912); // 324 x COP
    int tid = threadIdx.x;
    int bx = blockIdx.x, by = blockIdx.y, n = blockIdx.z;
    int y0 = by*16, x0 = bx*16;

    for (int idx = tid; idx < 1728; idx += 256) {
        int tap = idx / 192, r = idx % 192, o = r >> 6, c = r & 63;
        ws[idx] = w[(o*64 + c)*9 + tap];
    }
    for (int idx = tid; idx < 324*8; idx += 256) {
        int hp = idx >> 3, c8 = idx & 7;
        int yy = y0 + hp/18 - 1, xx = x0 + hp%18 - 1;
        uint4 val = make_uint4(0,0,0,0);
        if (yy >= 0 && yy < 128 && xx >= 0 && xx < 128)
            val = ((const uint4*)(h + (((size_t)n << 14) + (yy << 7) + xx)*64))[c8];
        ((uint4*)(hs + hp*COP))[c8] = val;
    }
    __syncthreads();

    int py = tid >> 4, px = tid & 15;
    float acc0 = 0.f, acc1 = 0.f, acc2 = 0.f;
    #pragma unroll
    for (int dy = 0; dy < 3; dy++)
        #pragma unroll
        for (int dx = 0; dx < 3; dx++) {
            int tap = dy*3 + dx;
            const __nv_bfloat16* hp = hs + ((py+dy)*18 + (px+dx))*COP;
            const float* wp = ws + tap*192;
            #pragma unroll
            for (int c8 = 0; c8 < 8; c8++) {
                uint4 hv = ((const uint4*)hp)[c8];
                float f[8] = { bflo(hv.x), bfhi(hv.x), bflo(hv.y), bfhi(hv.y),
                               bflo(hv.z), bfhi(hv.z), bflo(hv.w), bfhi(hv.w) };
                #pragma unroll
                for (int j = 0; j < 8; j++) {
                    int c = c8*8 + j;
                    acc0 = fmaf(f[j], wp[c      ], acc0);
                    acc1 = fmaf(f[j], wp[c +  64], acc1);
                    acc2 = fmaf(f[j], wp[c + 128], acc2);
                }
            }
        }

    int po = ((y0+py) << 7) + (x0+px);
    out[((n*3 + 0) << 14) + po] = acc0 + xin[((n*3 + 0) << 14) + po];
    out[((n*3 + 1) << 14) + po] = acc1 + xin[((n*3 + 1) << 14) + po];
    out[((n*3 + 2) << 14) + po] = acc2 + xin[((n*3 + 2) << 14) + po];
}

// ---------------------------------------------------------------------------
extern "C" void kernel_launch(void* const* d_in, const int* in_sizes, int n_in,
                              void* d_out, int out_size) {
    const float* x       = (const float*)d_in[0];
    const float* conv_in = (const float*)d_in[1];
    const float* W[9];
    for (int i = 0; i < 9; i++) W[i] = (const float*)d_in[2 + i];
    const float* conv_out = (const float*)d_in[11];
    float* out = (float*)d_out;

    __nv_bfloat16 *H0, *H1, *Q, *K, *V, *WB, *WCI;
    cudaGetSymbolAddress((void**)&H0, g_hb0);
    cudaGetSymbolAddress((void**)&H1, g_hb1);
    cudaGetSymbolAddress((void**)&Q,  g_qb);
    cudaGetSymbolAddress((void**)&K,  g_kb);
    cudaGetSymbolAddress((void**)&V,  g_vb);
    cudaGetSymbolAddress((void**)&WB, g_wb);
    cudaGetSymbolAddress((void**)&WCI, g_wci);

    size_t co_smem = 6912 + (size_t)324*COP*sizeof(__nv_bfloat16);   // ~53.6 KB
    cudaFuncSetAttribute(conv_out_k, cudaFuncAttributeMaxDynamicSharedMemorySize, (int)co_smem);

    convert_w_k<<<144, 256>>>(W[0], W[1], W[2], W[3], W[4], W[5], W[6], W[7], W[8], WB);
    convert_wc_k<<<16, 256>>>(conv_in, WCI);

    conv_in_k<<<dim3(16,16,8), 256>>>(x, WCI, H0);

    dim3 agrid(16, 32, 8);
    // layer 0: H0 -> H1
    qkv_k<<<NPIX/64, 256>>>(H0, WB, Q, K, V);
    attn_k<<<agrid, 256>>>(Q, K, V, H1);
    // layer 1: H1 -> H0
    qkv_k<<<NPIX/64, 256>>>(H1, WB + 192*64, Q, K, V);
    attn_k<<<agrid, 256>>>(Q, K, V, H0);
    // layer 2: H0 -> H1
    qkv_k<<<NPIX/64, 256>>>(H0, WB + 2*192*64, Q, K, V);
    attn_k<<<agrid, 256>>>(Q, K, V, H1);

    conv_out_k<<<dim3(8,8,8), 256, co_smem>>>(H1, conv_out, x, out);
}

// round 17
// speedup vs baseline: 1.1004x; 1.0579x over previous
#include <cuda_runtime.h>
#include <cuda_bf16.h>

#define NPIX (8*128*128)   // 131072 pixels
#define CCH  64

// Scratch (device globals). Activations NHWC.
__device__ __nv_bfloat16 g_hb0[(size_t)NPIX*CCH];
__device__ __nv_bfloat16 g_hb1[(size_t)NPIX*CCH];
__device__ __nv_bfloat16 g_qb[(size_t)NPIX*CCH];
__device__ __nv_bfloat16 g_kb[(size_t)NPIX*CCH];
__device__ __nv_bfloat16 g_vb[(size_t)NPIX*CCH];
__device__ __nv_bfloat16 g_wb[3*192*64];   // attn weights [w1;w2;w3], k contiguous
__device__ __nv_bfloat16 g_wci[64*64];     // conv_in weights [o][k], taps hi 0-26, lo 32-58

__device__ __forceinline__ unsigned pack_bf(float a, float b) {
    __nv_bfloat162 h = __floats2bfloat162_rn(a, b);
    return *reinterpret_cast<unsigned*>(&h);
}
__device__ __forceinline__ unsigned pack2h(__nv_bfloat16 a, __nv_bfloat16 b) {
    __nv_bfloat162 h = __halves2bfloat162(a, b);
    return *reinterpret_cast<unsigned*>(&h);
}
__device__ __forceinline__ void cp16(unsigned smem_dst, const void* gsrc) {
    asm volatile("cp.async.ca.shared.global [%0], [%1], 16;\n"
                 :: "r"(smem_dst), "l"(gsrc));
}
__device__ __forceinline__ float bflo(unsigned u) { return __uint_as_float(u << 16); }
__device__ __forceinline__ float bfhi(unsigned u) { return __uint_as_float(u & 0xffff0000u); }

#define MMA(c, a0,a1,a2,a3, b0,b1) \
    asm volatile("mma.sync.aligned.m16n8k16.row.col.f32.bf16.bf16.f32 " \
                 "{%0,%1,%2,%3}, {%4,%5,%6,%7}, {%8,%9}, {%0,%1,%2,%3};" \
                 : "+f"(c[0]), "+f"(c[1]), "+f"(c[2]), "+f"(c[3]) \
                 : "r"(a0), "r"(a1), "r"(a2), "r"(a3), "r"(b0), "r"(b1))

// ---------------------------------------------------------------------------
// weight converts (once per run)
// ---------------------------------------------------------------------------
__global__ void convert_w_k(const float* w0, const float* w1, const float* w2,
                            const float* w3, const float* w4, const float* w5,
                            const float* w6, const float* w7, const float* w8,
                            __nv_bfloat16* __restrict__ dst) {
    int idx = blockIdx.x*256 + threadIdx.x;
    if (idx >= 3*192*64) return;
    const float* tbl[9] = {w0,w1,w2,w3,w4,w5,w6,w7,w8};
    int layer = idx / 12288, r = idx % 12288;
    const float* src = tbl[layer*3 + r/4096];
    dst[idx] = __float2bfloat16(src[r & 4095]);
}

__global__ void convert_wc_k(const float* __restrict__ w, __nv_bfloat16* __restrict__ dst) {
    int idx = blockIdx.x*256 + threadIdx.x;
    if (idx >= 64*64) return;
    int o = idx >> 6, k = idx & 63;
    int t = k & 31;
    __nv_bfloat16 v = __float2bfloat16(0.f);
    if (t < 27) v = __float2bfloat16(w[o*27 + t]);
    dst[idx] = v;
}

// ---------------------------------------------------------------------------
// conv_in via tensor cores (round-16 proven): im2col A (hi/lo) @ W^T.
// ---------------------------------------------------------------------------
__global__ __launch_bounds__(256) void conv_in_k(const float* __restrict__ x,
                                                 const __nv_bfloat16* __restrict__ wci,
                                                 __nv_bfloat16* __restrict__ out) {
    __shared__ float xs[3][10][10];
    __shared__ __nv_bfloat16 a_s[64*72];
    __shared__ __nv_bfloat16 w_s[64*72];
    int tid = threadIdx.x;
    int bx = blockIdx.x, by = blockIdx.y, n = blockIdx.z;
    int y0 = by*8, x0 = bx*8;

    unsigned w_base = (unsigned)__cvta_generic_to_shared(w_s);
    #pragma unroll
    for (int i = 0; i < 2; i++) {
        int idx = tid + 256*i;
        int row = idx >> 3, c8 = idx & 7;
        cp16(w_base + row*144 + c8*16, wci + row*64 + c8*8);
    }
    asm volatile("cp.async.commit_group;\n" ::: "memory");

    for (int idx = tid; idx < 300; idx += 256) {
        int c = idx / 100, r = idx % 100;
        int yy = y0 + r/10 - 1, xx = x0 + r%10 - 1;
        float v = 0.f;
        if (yy >= 0 && yy < 128 && xx >= 0 && xx < 128)
            v = x[((n*3 + c) << 14) + (yy << 7) + xx];
        xs[c][r/10][r%10] = v;
    }
    asm volatile("cp.async.wait_group 0;\n" ::: "memory");
    __syncthreads();

    {
        int pxl = tid >> 2, kg = tid & 3;
        int ppy = pxl >> 3, ppx = pxl & 7;
        unsigned pk[8];
        #pragma unroll
        for (int j2 = 0; j2 < 8; j2++) {
            __nv_bfloat16 h0, h1;
            #pragma unroll
            for (int s = 0; s < 2; s++) {
                int k = kg*16 + j2*2 + s;
                int t = k & 31;
                bool lo = (k >= 32);
                __nv_bfloat16 hv = __float2bfloat16(0.f);
                if (t < 27) {
                    int c = t / 9, r = t % 9;
                    float xv = xs[c][ppy + r/3][ppx + r%3];
                    __nv_bfloat16 hb = __float2bfloat16(xv);
                    hv = lo ? __float2bfloat16(xv - __bfloat162float(hb)) : hb;
                }
                if (s == 0) h0 = hv; else h1 = hv;
            }
            pk[j2] = pack2h(h0, h1);
        }
        uint4* dst4 = (uint4*)(a_s + pxl*72 + kg*16);
        dst4[0] = make_uint4(pk[0], pk[1], pk[2], pk[3]);
        dst4[1] = make_uint4(pk[4], pk[5], pk[6], pk[7]);
    }
    __syncthreads();

    int lane = tid & 31, w = tid >> 5;
    int wm = (w >> 1) * 16;
    int wn = (w & 1) * 32;
    int lr = lane >> 2, lc = lane & 3;

    float c[4][4];
    #pragma unroll
    for (int t = 0; t < 4; t++)
        #pragma unroll
        for (int i = 0; i < 4; i++) c[t][i] = 0.f;

    #pragma unroll
    for (int ks = 0; ks < 4; ks++) {
        int k0 = ks*16;
        unsigned a0 = *(const unsigned*)&a_s[(wm+lr  )*72 + k0 + lc*2    ];
        unsigned a1 = *(const unsigned*)&a_s[(wm+lr+8)*72 + k0 + lc*2    ];
        unsigned a2 = *(const unsigned*)&a_s[(wm+lr  )*72 + k0 + lc*2 + 8];
        unsigned a3 = *(const unsigned*)&a_s[(wm+lr+8)*72 + k0 + lc*2 + 8];
        #pragma unroll
        for (int t = 0; t < 4; t++) {
            int bc = wn + t*8 + lr;
            unsigned b0 = *(const unsigned*)&w_s[bc*72 + k0 + lc*2    ];
            unsigned b1 = *(const unsigned*)&w_s[bc*72 + k0 + lc*2 + 8];
            MMA(c[t], a0,a1,a2,a3, b0,b1);
        }
    }

    int p0 = wm + lr, p1 = p0 + 8;
    size_t g0 = (((size_t)n << 14) + ((size_t)(y0 + (p0>>3)) << 7) + (x0 + (p0&7)))*64;
    size_t g1 = (((size_t)n << 14) + ((size_t)(y0 + (p1>>3)) << 7) + (x0 + (p1&7)))*64;
    #pragma unroll
    for (int t = 0; t < 4; t++) {
        int n0 = wn + t*8 + lc*2;
        *(unsigned*)(out + g0 + n0) = pack_bf(fmaxf(c[t][0],0.f), fmaxf(c[t][1],0.f));
        *(unsigned*)(out + g1 + n0) = pack_bf(fmaxf(c[t][2],0.f), fmaxf(c[t][3],0.f));
    }
}

// ---------------------------------------------------------------------------
// qkv: fused triple 1x1 via bf16 mma, DOUBLE-BUFFERED 2x64px tiles per block.
// W staged once (group 0 with A0); A1 streams in during tile-0 compute.
// ---------------------------------------------------------------------------
__global__ __launch_bounds__(256) void qkv_k(const __nv_bfloat16* __restrict__ in,
                                             const __nv_bfloat16* __restrict__ wb,
                                             __nv_bfloat16* __restrict__ qo,
                                             __nv_bfloat16* __restrict__ ko,
                                             __nv_bfloat16* __restrict__ vo) {
    __shared__ __nv_bfloat16 a_s[2][64*72];
    __shared__ __nv_bfloat16 w_s[192*72];
    int tid = threadIdx.x;
    size_t pix0 = (size_t)blockIdx.x * 128;

    unsigned a0_base = (unsigned)__cvta_generic_to_shared(a_s[0]);
    unsigned a1_base = (unsigned)__cvta_generic_to_shared(a_s[1]);
    unsigned w_base  = (unsigned)__cvta_generic_to_shared(w_s);

    // group 0: W + A0
    #pragma unroll
    for (int i = 0; i < 6; i++) {
        int idx = tid + 256*i;
        int row = idx >> 3, c8 = idx & 7;
        cp16(w_base + row*144 + c8*16, wb + row*64 + c8*8);
    }
    #pragma unroll
    for (int i = 0; i < 2; i++) {
        int idx = tid + 256*i;
        int row = idx >> 3, c8 = idx & 7;
        cp16(a0_base + row*144 + c8*16, in + pix0*64 + (size_t)idx*8);
    }
    asm volatile("cp.async.commit_group;\n" ::: "memory");
    // group 1: A1
    #pragma unroll
    for (int i = 0; i < 2; i++) {
        int idx = tid + 256*i;
        int row = idx >> 3, c8 = idx & 7;
        cp16(a1_base + row*144 + c8*16, in + (pix0 + 64)*64 + (size_t)idx*8);
    }
    asm volatile("cp.async.commit_group;\n" ::: "memory");

    int lane = tid & 31, w = tid >> 5;
    int wm = (w >> 1) * 16;
    int wn = (w & 1) * 96;
    int lr = lane >> 2, lc = lane & 3;

    asm volatile("cp.async.wait_group 1;\n" ::: "memory");   // W + A0 ready
    __syncthreads();

    #pragma unroll
    for (int tile = 0; tile < 2; tile++) {
        const __nv_bfloat16* at = a_s[tile];
        float c[12][4];
        #pragma unroll
        for (int t = 0; t < 12; t++)
            #pragma unroll
            for (int i = 0; i < 4; i++) c[t][i] = 0.f;

        #pragma unroll
        for (int ks = 0; ks < 4; ks++) {
            int k0 = ks*16;
            unsigned a0 = *(const unsigned*)&at[(wm+lr  )*72 + k0 + lc*2    ];
            unsigned a1 = *(const unsigned*)&at[(wm+lr+8)*72 + k0 + lc*2    ];
            unsigned a2 = *(const unsigned*)&at[(wm+lr  )*72 + k0 + lc*2 + 8];
            unsigned a3 = *(const unsigned*)&at[(wm+lr+8)*72 + k0 + lc*2 + 8];
            #pragma unroll
            for (int t = 0; t < 12; t++) {
                int bc = wn + t*8 + lr;
                unsigned b0 = *(const unsigned*)&w_s[bc*72 + k0 + lc*2    ];
                unsigned b1 = *(const unsigned*)&w_s[bc*72 + k0 + lc*2 + 8];
                MMA(c[t], a0,a1,a2,a3, b0,b1);
            }
        }

        size_t pixA = pix0 + tile*64 + wm + lr;
        size_t pixB = pixA + 8;
        #pragma unroll
        for (int t = 0; t < 12; t++) {
            int n0 = wn + t*8 + lc*2;
            __nv_bfloat16* dst = (n0 < 64) ? qo : (n0 < 128) ? ko : vo;
            int ch = n0 & 63;
            *(unsigned*)(dst + pixA*64 + ch) = pack_bf(c[t][0], c[t][1]);
            *(unsigned*)(dst + pixB*64 + ch) = pack_bf(c[t][2], c[t][3]);
        }

        if (tile == 0) {
            asm volatile("cp.async.wait_group 0;\n" ::: "memory");   // A1 ready
            __syncthreads();
        }
    }
}

// ---------------------------------------------------------------------------
// attn: 5x5 local attention + relu (round-14 math; occupancy 4->5 CTAs/SM).
// ---------------------------------------------------------------------------
#define KROW8 72

__global__ __launch_bounds__(256, 5) void attn_k(const __nv_bfloat16* __restrict__ xq,
                                                 const __nv_bfloat16* __restrict__ xk,
                                                 const __nv_bfloat16* __restrict__ xv,
                                                 __nv_bfloat16* __restrict__ outb) {
    __shared__ __nv_bfloat16 k_s[96*KROW8];
    __shared__ __nv_bfloat16 v_s[96*KROW8];
    __shared__ float wgt_s[32*26];
    int tid = threadIdx.x;
    int bx = blockIdx.x, by = blockIdx.y, n = blockIdx.z;
    int y0 = by*4, x0 = bx*8;

    for (int idx = tid; idx < 96*8; idx += 256) {
        int hp = idx >> 3, c8 = idx & 7;
        int yy = y0 + (hp/12) - 2, xx = x0 + (hp%12) - 2;
        uint4 kv = make_uint4(0,0,0,0), vv = make_uint4(0,0,0,0);
        if (yy >= 0 && yy < 128 && xx >= 0 && xx < 128) {
            size_t base = (((size_t)n << 14) + (yy << 7) + xx) * 8;
            kv = ((const uint4*)xk)[base + c8];
            vv = ((const uint4*)xv)[base + c8];
        }
        ((uint4*)(k_s + hp*KROW8))[c8] = kv;
        ((uint4*)(v_s + hp*KROW8))[c8] = vv;
    }
    __syncthreads();

    int pix = tid >> 3, q = tid & 7;
    int py = pix >> 3, px = pix & 7;

    float qr[8];
    {
        size_t gb = (((size_t)n << 14) + ((size_t)(y0+py) << 7) + (x0+px))*64 + q*8;
        uint4 uq = *(const uint4*)(xq + gb);
        qr[0]=bflo(uq.x); qr[1]=bfhi(uq.x); qr[2]=bflo(uq.y); qr[3]=bfhi(uq.y);
        qr[4]=bflo(uq.z); qr[5]=bfhi(uq.z); qr[6]=bflo(uq.w); qr[7]=bfhi(uq.w);
    }

    float m = -1e30f;
    #pragma unroll
    for (int dy = 0; dy < 5; dy++)
        #pragma unroll
        for (int dx = 0; dx < 5; dx++) {
            int nb = (py+dy)*12 + (px+dx);
            uint4 ka = *(const uint4*)(k_s + nb*KROW8 + q*8);
            float s = 0.f;
            s = fmaf(bflo(ka.x), qr[0], s); s = fmaf(bfhi(ka.x), qr[1], s);
            s = fmaf(bflo(ka.y), qr[2], s); s = fmaf(bfhi(ka.y), qr[3], s);
            s = fmaf(bflo(ka.z), qr[4], s); s = fmaf(bfhi(ka.z), qr[5], s);
            s = fmaf(bflo(ka.w), qr[6], s); s = fmaf(bfhi(ka.w), qr[7], s);
            s += __shfl_xor_sync(0xffffffffu, s, 1);
            s += __shfl_xor_sync(0xffffffffu, s, 2);
            s += __shfl_xor_sync(0xffffffffu, s, 4);
            wgt_s[pix*26 + dy*5 + dx] = s;
            m = fmaxf(m, s);
        }
    __syncwarp();

    float psum = 0.f;
    for (int t = q; t < 25; t += 8) {
        float e = __expf(wgt_s[pix*26 + t] - m);
        wgt_s[pix*26 + t] = e;
        psum += e;
    }
    psum += __shfl_xor_sync(0xffffffffu, psum, 1);
    psum += __shfl_xor_sync(0xffffffffu, psum, 2);
    psum += __shfl_xor_sync(0xffffffffu, psum, 4);
    float inv = 1.f / psum;
    __syncwarp();

    float o[8];
    #pragma unroll
    for (int i = 0; i < 8; i++) o[i] = 0.f;
    #pragma unroll
    for (int dy = 0; dy < 5; dy++)
        #pragma unroll
        for (int dx = 0; dx < 5; dx++) {
            int nb = (py+dy)*12 + (px+dx);
            float wk = wgt_s[pix*26 + dy*5 + dx];
            uint4 va = *(const uint4*)(v_s + nb*KROW8 + q*8);
            o[0] = fmaf(wk, bflo(va.x), o[0]); o[1] = fmaf(wk, bfhi(va.x), o[1]);
            o[2] = fmaf(wk, bflo(va.y), o[2]); o[3] = fmaf(wk, bfhi(va.y), o[3]);
            o[4] = fmaf(wk, bflo(va.z), o[4]); o[5] = fmaf(wk, bfhi(va.z), o[5]);
            o[6] = fmaf(wk, bflo(va.w), o[6]); o[7] = fmaf(wk, bfhi(va.w), o[7]);
        }

    size_t base = (((size_t)n << 14) + ((size_t)(y0+py) << 7) + (x0+px))*64 + q*8;
    uint4 u = make_uint4(pack_bf(fmaxf(o[0]*inv,0.f), fmaxf(o[1]*inv,0.f)),
                         pack_bf(fmaxf(o[2]*inv,0.f), fmaxf(o[3]*inv,0.f)),
                         pack_bf(fmaxf(o[4]*inv,0.f), fmaxf(o[5]*inv,0.f)),
                         pack_bf(fmaxf(o[6]*inv,0.f), fmaxf(o[7]*inv,0.f)));
    *(uint4*)(outb + base) = u;
}

// ---------------------------------------------------------------------------
// conv_out + residual: h NHWC bf16 -> conv3x3 (64->3) + x -> NCHW fp32.
// ---------------------------------------------------------------------------
#define COP 72

__global__ __launch_bounds__(256) void conv_out_k(const __nv_bfloat16* __restrict__ h,
                                                  const float* __restrict__ w,
                                                  const float* __restrict__ xin,
                                                  float* __restrict__ out) {
    extern __shared__ char smc[];
    float* ws = (float*)smc;                          // 1728 floats [tap][o][c]
    __nv_bfloat16* hs = (__nv_bfloat16*)(smc + 6912); // 324 x COP
    int tid = threadIdx.x;
    int bx = blockIdx.x, by = blockIdx.y, n = blockIdx.z;
    int y0 = by*16, x0 = bx*16;

    for (int idx = tid; idx < 1728; idx += 256) {
        int tap = idx / 192, r = idx % 192, o = r >> 6, c = r & 63;
        ws[idx] = w[(o*64 + c)*9 + tap];
    }
    for (int idx = tid; idx < 324*8; idx += 256) {
        int hp = idx >> 3, c8 = idx & 7;
        int yy = y0 + hp/18 - 1, xx = x0 + hp%18 - 1;
        uint4 val = make_uint4(0,0,0,0);
        if (yy >= 0 && yy < 128 && xx >= 0 && xx < 128)
            val = ((const uint4*)(h + (((size_t)n << 14) + (yy << 7) + xx)*64))[c8];
        ((uint4*)(hs + hp*COP))[c8] = val;
    }
    __syncthreads();

    int py = tid >> 4, px = tid & 15;
    float acc0 = 0.f, acc1 = 0.f, acc2 = 0.f;
    #pragma unroll
    for (int dy = 0; dy < 3; dy++)
        #pragma unroll
        for (int dx = 0; dx < 3; dx++) {
            int tap = dy*3 + dx;
            const __nv_bfloat16* hp = hs + ((py+dy)*18 + (px+dx))*COP;
            const float* wp = ws + tap*192;
            #pragma unroll
            for (int c8 = 0; c8 < 8; c8++) {
                uint4 hv = ((const uint4*)hp)[c8];
                float f[8] = { bflo(hv.x), bfhi(hv.x), bflo(hv.y), bfhi(hv.y),
                               bflo(hv.z), bfhi(hv.z), bflo(hv.w), bfhi(hv.w) };
                #pragma unroll
                for (int j = 0; j < 8; j++) {
                    int c = c8*8 + j;
                    acc0 = fmaf(f[j], wp[c      ], acc0);
                    acc1 = fmaf(f[j], wp[c +  64], acc1);
                    acc2 = fmaf(f[j], wp[c + 128], acc2);
                }
            }
        }

    int po = ((y0+py) << 7) + (x0+px);
    out[((n*3 + 0) << 14) + po] = acc0 + xin[((n*3 + 0) << 14) + po];
    out[((n*3 + 1) << 14) + po] = acc1 + xin[((n*3 + 1) << 14) + po];
    out[((n*3 + 2) << 14) + po] = acc2 + xin[((n*3 + 2) << 14) + po];
}

// ---------------------------------------------------------------------------
extern "C" void kernel_launch(void* const* d_in, const int* in_sizes, int n_in,
                              void* d_out, int out_size) {
    const float* x       = (const float*)d_in[0];
    const float* conv_in = (const float*)d_in[1];
    const float* W[9];
    for (int i = 0; i < 9; i++) W[i] = (const float*)d_in[2 + i];
    const float* conv_out = (const float*)d_in[11];
    float* out = (float*)d_out;

    __nv_bfloat16 *H0, *H1, *Q, *K, *V, *WB, *WCI;
    cudaGetSymbolAddress((void**)&H0, g_hb0);
    cudaGetSymbolAddress((void**)&H1, g_hb1);
    cudaGetSymbolAddress((void**)&Q,  g_qb);
    cudaGetSymbolAddress((void**)&K,  g_kb);
    cudaGetSymbolAddress((void**)&V,  g_vb);
    cudaGetSymbolAddress((void**)&WB, g_wb);
    cudaGetSymbolAddress((void**)&WCI, g_wci);

    size_t co_smem = 6912 + (size_t)324*COP*sizeof(__nv_bfloat16);   // ~53.6 KB
    cudaFuncSetAttribute(conv_out_k, cudaFuncAttributeMaxDynamicSharedMemorySize, (int)co_smem);

    convert_w_k<<<144, 256>>>(W[0], W[1], W[2], W[3], W[4], W[5], W[6], W[7], W[8], WB);
    convert_wc_k<<<16, 256>>>(conv_in, WCI);

    conv_in_k<<<dim3(16,16,8), 256>>>(x, WCI, H0);

    dim3 agrid(16, 32, 8);
    // layer 0: H0 -> H1
    qkv_k<<<NPIX/128, 256>>>(H0, WB, Q, K, V);
    attn_k<<<agrid, 256>>>(Q, K, V, H1);
    // layer 1: H1 -> H0
    qkv_k<<<NPIX/128, 256>>>(H1, WB + 192*64, Q, K, V);
    attn_k<<<agrid, 256>>>(Q, K, V, H0);
    // layer 2: H0 -> H1
    qkv_k<<<NPIX/128, 256>>>(H0, WB + 2*192*64, Q, K, V);
    attn_k<<<agrid, 256>>>(Q, K, V, H1);

    conv_out_k<<<dim3(8,8,8), 256, co_smem>>>(H1, conv_out, x, out);
}